// round 17
// baseline (speedup 1.0000x reference)
#include <cuda_runtime.h>
#include <cuda_fp16.h>
#include <cstdint>

// ---------------- fixed problem dimensions ----------------------------------
#define NNODES 204800
#define NEDGES 409600
#define INCH   128
#define HID    256
#define NCOMP  8192
#define NGRAPH 4096
#define NPC    25
#define CPG    2
#define SDIM   64
#define MSET   8
#define KWC    512
#define NBLK   800            // NNODES / 256

// ---------------- scratch ----------------------------------------------------
__device__ __half g_hsum[(size_t)NNODES * HID];
__device__ __half g_h  [(size_t)NNODES * HID];
__device__ __half g_cm [NCOMP * HID];
__device__ float g_tt  [NCOMP * KWC];
__device__ float g_pool[NGRAPH * SDIM];
__device__ float g_tfc [NGRAPH * 32];
__device__ float g_stats[64];

// CSR scratch
__device__ int g_deg [NNODES];
__device__ int g_offp[NNODES];
__device__ int g_off [NNODES];
__device__ int g_cur [NNODES];
__device__ int g_bsum[1024];
__device__ int g_csrc[NEDGES];

// transposed weights, single fp16, [N][K] K-major
#define OFF_W0A  0
#define OFF_W0B  32768
#define OFF_WRA0 98304
#define OFF_WRB0 163840
#define OFF_WRA1 229376
#define OFF_WRB1 294912
#define OFF_WC   360448
#define WT_TOTAL 491520
__device__ __half g_wt[WT_TOTAL];

// ---------------- helpers ------------------------------------------------------
__device__ __forceinline__ uint32_t smem_u32(const void* p) {
    uint32_t a;
    asm("{ .reg .u64 t; cvta.to.shared.u64 t, %1; cvt.u32.u64 %0, t; }" : "=r"(a) : "l"(p));
    return a;
}

#define LDSM_X4(r0, r1, r2, r3, addr)                                          \
    asm volatile("ldmatrix.sync.aligned.m8n8.x4.shared.b16 {%0,%1,%2,%3}, [%4];" \
                 : "=r"(r0), "=r"(r1), "=r"(r2), "=r"(r3) : "r"(addr))

#define MMA_F16(d, a0, a1, a2, a3, b0, b1)                                     \
    asm volatile("mma.sync.aligned.m16n8k16.row.col.f32.f16.f16.f32 "          \
                 "{%0,%1,%2,%3}, {%4,%5,%6,%7}, {%8,%9}, {%0,%1,%2,%3};"       \
                 : "+f"((d)[0]), "+f"((d)[1]), "+f"((d)[2]), "+f"((d)[3])      \
                 : "r"(a0), "r"(a1), "r"(a2), "r"(a3), "r"(b0), "r"(b1))

#define CP_ASYNC_16(saddr, gptr)                                               \
    asm volatile("cp.async.cg.shared.global [%0], [%1], 16;"                   \
                 :: "r"(saddr), "l"(gptr))
#define CP_COMMIT()  asm volatile("cp.async.commit_group;" ::: "memory")
#define CP_WAIT0()   asm volatile("cp.async.wait_group 0;" ::: "memory")
#define CP_WAIT1()   asm volatile("cp.async.wait_group 1;" ::: "memory")

#define ROWB 80
#define WBUF 10240             // 128 rows * 80B, one 32-k chunk

// ---------------- merged weight transpose --------------------------------------
__global__ void transpose_all(const float* __restrict__ w0a, const float* __restrict__ w0b,
                              const float* __restrict__ wra, const float* __restrict__ wrb,
                              const float* __restrict__ Wc) {
    int i = blockIdx.x * 256 + threadIdx.x;
    if (i >= WT_TOTAL) return;
    const float* srcs[7] = {w0a, w0b, wra, wrb + 0, wra + HID * HID, wrb + HID * HID, Wc};
    const int dof[8] = {OFF_W0A, OFF_W0B, OFF_WRA0, OFF_WRB0, OFF_WRA1, OFF_WRB1, OFF_WC, WT_TOTAL};
    const int Ks[7] = {INCH, HID, HID, HID, HID, HID, HID};
    const int Ns[7] = {HID, HID, HID, HID, HID, HID, KWC};
    int r = 0;
#pragma unroll
    for (int q = 1; q < 7; q++) if (i >= dof[q]) r = q;
    int local = i - dof[r];
    int K = Ks[r], N = Ns[r];
    int k = local / N, n = local % N;
    g_wt[(size_t)dof[r] + (size_t)n * K + k] = __float2half(srcs[r][local]);
}

// ---------------- CSR build -----------------------------------------------------
__global__ void csr_zero() {
    int i = blockIdx.x * 256 + threadIdx.x;
    if (i < NNODES) g_deg[i] = 0;
}
__global__ void csr_count(const int* __restrict__ dst) {
    int e = blockIdx.x * 256 + threadIdx.x;
    if (e < NEDGES) atomicAdd(&g_deg[dst[e]], 1);
}
__global__ void csr_scan1() {
    __shared__ int s[256];
    int i = blockIdx.x * 256 + threadIdx.x;
    int v = g_deg[i];
    s[threadIdx.x] = v;
    __syncthreads();
#pragma unroll
    for (int d = 1; d < 256; d <<= 1) {
        int t = (threadIdx.x >= d) ? s[threadIdx.x - d] : 0;
        __syncthreads();
        s[threadIdx.x] += t;
        __syncthreads();
    }
    g_offp[i] = s[threadIdx.x] - v;
    if (threadIdx.x == 255) g_bsum[blockIdx.x] = s[255];
}
__global__ void csr_scan2() {
    __shared__ int s[1024];
    int t = threadIdx.x;
    int v = (t < NBLK) ? g_bsum[t] : 0;
    s[t] = v;
    __syncthreads();
#pragma unroll
    for (int d = 1; d < 1024; d <<= 1) {
        int u = (t >= d) ? s[t - d] : 0;
        __syncthreads();
        s[t] += u;
        __syncthreads();
    }
    if (t < NBLK) g_bsum[t] = s[t] - v;
}
__global__ void csr_scan3() {
    int i = blockIdx.x * 256 + threadIdx.x;
    if (i >= NNODES) return;
    int o = g_offp[i] + g_bsum[i >> 8];
    g_off[i] = o;
    g_cur[i] = o;
}
__global__ void csr_fill(const int* __restrict__ src, const int* __restrict__ dst) {
    int e = blockIdx.x * 256 + threadIdx.x;
    if (e >= NEDGES) return;
    int pos = atomicAdd(&g_cur[dst[e]], 1);
    g_csrc[pos] = src[e];
}

// ---------------- gathers --------------------------------------------------------
template <int CH>
__global__ void gather_f32(const float* __restrict__ xin) {
    int node = blockIdx.x * 8 + (threadIdx.x >> 5);
    int lane = threadIdx.x & 31;
    if (node >= NNODES) return;
    int beg = g_off[node];
    int deg = g_deg[node];
    float4 acc[CH / 128];
    const float* xr = xin + (size_t)node * CH;
#pragma unroll
    for (int j = 0; j < CH / 128; j++) acc[j] = *(const float4*)(xr + j * 128 + lane * 4);
    for (int e = beg; e < beg + deg; e++) {
        int s = g_csrc[e];
        const float* xs = xin + (size_t)s * CH;
#pragma unroll
        for (int j = 0; j < CH / 128; j++) {
            float4 v = *(const float4*)(xs + j * 128 + lane * 4);
            acc[j].x += v.x; acc[j].y += v.y; acc[j].z += v.z; acc[j].w += v.w;
        }
    }
    __half* op = g_hsum + (size_t)node * CH;
#pragma unroll
    for (int j = 0; j < CH / 128; j++) {
        union { __half2 h[2]; uint2 u; } o;
        o.h[0] = __floats2half2_rn(acc[j].x, acc[j].y);
        o.h[1] = __floats2half2_rn(acc[j].z, acc[j].w);
        *(uint2*)(op + j * 128 + lane * 4) = o.u;
    }
}

template <int CH>
__global__ void gather_f16(const __half* __restrict__ xin) {
    int node = blockIdx.x * 8 + (threadIdx.x >> 5);
    int lane = threadIdx.x & 31;
    if (node >= NNODES) return;
    int beg = g_off[node];
    int deg = g_deg[node];
    float acc[CH / 128][4];
    const __half* xr = xin + (size_t)node * CH;
#pragma unroll
    for (int j = 0; j < CH / 128; j++) {
        union { uint2 u; __half2 h[2]; } v;
        v.u = *(const uint2*)(xr + j * 128 + lane * 4);
        float2 a = __half22float2(v.h[0]), b = __half22float2(v.h[1]);
        acc[j][0] = a.x; acc[j][1] = a.y; acc[j][2] = b.x; acc[j][3] = b.y;
    }
    for (int e = beg; e < beg + deg; e++) {
        int s = g_csrc[e];
        const __half* xs = xin + (size_t)s * CH;
#pragma unroll
        for (int j = 0; j < CH / 128; j++) {
            union { uint2 u; __half2 h[2]; } v;
            v.u = *(const uint2*)(xs + j * 128 + lane * 4);
            float2 a = __half22float2(v.h[0]), b = __half22float2(v.h[1]);
            acc[j][0] += a.x; acc[j][1] += a.y; acc[j][2] += b.x; acc[j][3] += b.y;
        }
    }
    __half* op = g_hsum + (size_t)node * CH;
#pragma unroll
    for (int j = 0; j < CH / 128; j++) {
        union { __half2 h[2]; uint2 u; } o;
        o.h[0] = __floats2half2_rn(acc[j][0], acc[j][1]);
        o.h[1] = __floats2half2_rn(acc[j][2], acc[j][3]);
        *(uint2*)(op + j * 128 + lane * 4) = o.u;
    }
}

// ---------------- fused conv MLP: h = act2(relu(A@W1+b1)@W2+b2) ------------------
// CTA = 128 rows. Phase1: two N-halves into t1 smem. Phase2: t1 smem @ W2 -> global.
template <int K1, int ACT2>   // ACT2: 1 relu, 0 none
__global__ void __launch_bounds__(256)
fused_mlp(const __half* __restrict__ A, const __half* __restrict__ W1,
          const float* __restrict__ b1, const __half* __restrict__ W2,
          const float* __restrict__ b2, __half* __restrict__ Hout) {
    extern __shared__ char smem[];
    constexpr int ROWA = K1 * 2 + 16;
    constexpr int ROWT = HID * 2 + 16;       // 528
    constexpr int ASZ = 128 * ROWA;
    constexpr int TSZ = 128 * ROWT;
    const uint32_t sb = smem_u32(smem);
    const uint32_t aBase = sb;
    const uint32_t tBase = sb + ASZ;
    const uint32_t wBase = sb + ASZ + TSZ;
    char* const smemc = smem;

    const int tid = threadIdx.x;
    const int lane = tid & 31, wid = tid >> 5;
    const int wm = wid >> 2, wn = wid & 3;
    const int m0 = blockIdx.x * 128;

    float acc[4][4][4];

    auto zeroAcc = [&]() {
#pragma unroll
        for (int i = 0; i < 4; i++)
#pragma unroll
            for (int j = 0; j < 4; j++)
#pragma unroll
                for (int q = 0; q < 4; q++) acc[i][j][q] = 0.f;
    };

    const int lrow = tid >> 2, lc = tid & 3;           // loaders: 64 rows/iter

    auto loadA = [&](int c) {
#pragma unroll
        for (int i = 0; i < 2; i++) {
            int row = lrow + i * 64;
            CP_ASYNC_16(aBase + (uint32_t)row * ROWA + c * 64 + lc * 16,
                        A + (size_t)(m0 + row) * K1 + c * 32 + lc * 8);
        }
    };
    auto loadW = [&](const __half* Wp, int Kw, int c, int buf) {
        uint32_t sd = wBase + buf * WBUF;
#pragma unroll
        for (int i = 0; i < 2; i++) {
            int row = lrow + i * 64;
            CP_ASYNC_16(sd + (uint32_t)row * ROWB + lc * 16,
                        Wp + (size_t)row * Kw + c * 32 + lc * 8);
        }
    };

    auto computeChunk = [&](uint32_t aB, int rstride, uint32_t wB, int c) {
#pragma unroll
        for (int k16 = 0; k16 < 2; k16++) {
            uint32_t kadd = k16 * 32;
            uint32_t bh[8];
            uint32_t bo = wB + (uint32_t)(wn * 32 + (lane & 7) + (lane >> 4) * 8) * ROWB +
                          ((lane >> 3) & 1) * 16 + kadd;
            LDSM_X4(bh[0], bh[1], bh[2], bh[3], bo);
            LDSM_X4(bh[4], bh[5], bh[6], bh[7], bo + 16 * ROWB);
#pragma unroll
            for (int mi = 0; mi < 4; mi++) {
                uint32_t a0, a1, a2, a3;
                uint32_t ao = aB + (uint32_t)(wm * 64 + (lane & 15) + mi * 16) * rstride +
                              (lane >> 4) * 16 + c * 64 + kadd;
                LDSM_X4(a0, a1, a2, a3, ao);
#pragma unroll
                for (int ni = 0; ni < 4; ni++)
                    MMA_F16(acc[mi][ni], a0, a1, a2, a3, bh[ni * 2], bh[ni * 2 + 1]);
            }
        }
    };

    const int nch1 = K1 / 32, nch2 = HID / 32;

    // ================= PHASE 1: t1 = relu(A @ W1 + b1) =================
#pragma unroll 1
    for (int hf = 0; hf < 2; hf++) {
        zeroAcc();
        const __half* Wp = W1 + (size_t)hf * 128 * K1;
        if (hf == 0) loadA(0);
        loadW(Wp, K1, 0, 0);
        CP_COMMIT(); CP_WAIT0();
        __syncthreads();
#pragma unroll 1
        for (int c = 0; c < nch1; c++) {
            if (c + 1 < nch1) {
                if (hf == 0) loadA(c + 1);
                loadW(Wp, K1, c + 1, (c + 1) & 1);
                CP_COMMIT();
            }
            computeChunk(aBase, ROWA, wBase + (c & 1) * WBUF, c);
            if (c + 1 < nch1) { CP_WAIT0(); __syncthreads(); }
        }
        __syncthreads();
        // epilogue -> t1 smem (relu + bias)
#pragma unroll
        for (int ni = 0; ni < 4; ni++) {
            int col = hf * 128 + wn * 32 + ni * 8 + (lane & 3) * 2;
            float bb0 = __ldg(b1 + col), bb1 = __ldg(b1 + col + 1);
#pragma unroll
            for (int mi = 0; mi < 4; mi++) {
                int row = wm * 64 + mi * 16 + (lane >> 2);
                float v0 = fmaxf(acc[mi][ni][0] + bb0, 0.f);
                float v1 = fmaxf(acc[mi][ni][1] + bb1, 0.f);
                float v2 = fmaxf(acc[mi][ni][2] + bb0, 0.f);
                float v3 = fmaxf(acc[mi][ni][3] + bb1, 0.f);
                union { __half2 h; uint32_t u; } p0, p1;
                p0.h = __floats2half2_rn(v0, v1);
                p1.h = __floats2half2_rn(v2, v3);
                *(uint32_t*)(smemc + ASZ + (size_t)row * ROWT + col * 2) = p0.u;
                *(uint32_t*)(smemc + ASZ + (size_t)(row + 8) * ROWT + col * 2) = p1.u;
            }
        }
    }
    __syncthreads();   // t1 fully written

    // ================= PHASE 2: h = act2(t1 @ W2 + b2) =================
#pragma unroll 1
    for (int hf = 0; hf < 2; hf++) {
        zeroAcc();
        const __half* Wp = W2 + (size_t)hf * 128 * HID;
        loadW(Wp, HID, 0, 0);
        CP_COMMIT(); CP_WAIT0();
        __syncthreads();
#pragma unroll 1
        for (int c = 0; c < nch2; c++) {
            if (c + 1 < nch2) { loadW(Wp, HID, c + 1, (c + 1) & 1); CP_COMMIT(); }
            computeChunk(tBase, ROWT, wBase + (c & 1) * WBUF, c);
            if (c + 1 < nch2) { CP_WAIT0(); __syncthreads(); }
        }
        __syncthreads();
        // epilogue -> global fp16
#pragma unroll
        for (int ni = 0; ni < 4; ni++) {
            int col = hf * 128 + wn * 32 + ni * 8 + (lane & 3) * 2;
            float bb0 = __ldg(b2 + col), bb1 = __ldg(b2 + col + 1);
#pragma unroll
            for (int mi = 0; mi < 4; mi++) {
                int row = m0 + wm * 64 + mi * 16 + (lane >> 2);
                float v0 = acc[mi][ni][0] + bb0, v1 = acc[mi][ni][1] + bb1;
                float v2 = acc[mi][ni][2] + bb0, v3 = acc[mi][ni][3] + bb1;
                if (ACT2 == 1) {
                    v0 = fmaxf(v0, 0.f); v1 = fmaxf(v1, 0.f);
                    v2 = fmaxf(v2, 0.f); v3 = fmaxf(v3, 0.f);
                }
                union { __half2 h; uint32_t u; } p0, p1;
                p0.h = __floats2half2_rn(v0, v1);
                p1.h = __floats2half2_rn(v2, v3);
                *(uint32_t*)(Hout + (size_t)row * HID + col) = p0.u;
                *(uint32_t*)(Hout + (size_t)(row + 8) * HID + col) = p1.u;
            }
        }
    }
}

// ---------------- standalone GEMM (set-rep), 3-stage pipeline -------------------
#define AHI 0
#define BHI 10240
#define STAGE 20480
#define GEMM_SMEM (3 * STAGE)

template <int ACT>
__global__ void __launch_bounds__(256)
mma_gemm(const __half* __restrict__ A, const __half* __restrict__ Bt,
         const float* __restrict__ bias, float* __restrict__ C, int K, int N) {
    extern __shared__ char smem[];
    const uint32_t sb = smem_u32(smem);
    const int tid = threadIdx.x;
    const int lane = tid & 31, wid = tid >> 5;
    const int wm = wid >> 2, wn = wid & 3;
    const int m0 = blockIdx.y * 128, n0 = blockIdx.x * 128;

    const __half* Ab = A + (size_t)m0 * K;
    const __half* Bp = Bt + (size_t)n0 * K;

    float acc[4][4][4];
#pragma unroll
    for (int i = 0; i < 4; i++)
#pragma unroll
        for (int j = 0; j < 4; j++)
#pragma unroll
            for (int q = 0; q < 4; q++) acc[i][j][q] = 0.f;

    const uint32_t aOff = (uint32_t)(wm * 64 + (lane & 15)) * ROWB + (lane >> 4) * 16;
    const uint32_t bOff = (uint32_t)(wn * 32 + (lane & 7) + (lane >> 4) * 8) * ROWB +
                          ((lane >> 3) & 1) * 16;

    const int arow = tid >> 2, ac8 = tid & 3;

    auto asyncAll = [&](int buf, int k0) {
        uint32_t sd = sb + buf * STAGE;
#pragma unroll
        for (int i = 0; i < 2; i++) {
            int row = arow + i * 64;
            uint32_t so = row * ROWB + ac8 * 16;
            CP_ASYNC_16(sd + AHI + so, Ab + (size_t)row * K + k0 + ac8 * 8);
            CP_ASYNC_16(sd + BHI + so, Bp + (size_t)row * K + k0 + ac8 * 8);
        }
    };

    auto compute = [&](int buf) {
        uint32_t sa = sb + buf * STAGE;
#pragma unroll
        for (int k16 = 0; k16 < 2; k16++) {
            uint32_t kadd = k16 * 32;
            uint32_t bh[8];
#pragma unroll
            for (int p = 0; p < 2; p++) {
                LDSM_X4(bh[p * 4 + 0], bh[p * 4 + 1], bh[p * 4 + 2], bh[p * 4 + 3],
                        sa + BHI + bOff + p * (16 * ROWB) + kadd);
            }
#pragma unroll
            for (int mi = 0; mi < 4; mi++) {
                uint32_t a0, a1, a2, a3;
                LDSM_X4(a0, a1, a2, a3, sa + AHI + aOff + mi * (16 * ROWB) + kadd);
#pragma unroll
                for (int ni = 0; ni < 4; ni++)
                    MMA_F16(acc[mi][ni], a0, a1, a2, a3, bh[ni * 2], bh[ni * 2 + 1]);
            }
        }
    };

    const int nchunk = K / 32;
    asyncAll(0, 0); CP_COMMIT();
    if (nchunk > 1) { asyncAll(1, 32); CP_COMMIT(); CP_WAIT1(); }
    else CP_WAIT0();
    __syncthreads();

    for (int c = 0; c < nchunk; c++) {
        compute(c % 3);
        bool more = (c + 2 < nchunk);
        if (more) { asyncAll((c + 2) % 3, (c + 2) * 32); CP_COMMIT(); }
        if (c + 1 < nchunk) {
            if (more) CP_WAIT1(); else CP_WAIT0();
            __syncthreads();
        }
    }

#pragma unroll
    for (int ni = 0; ni < 4; ni++) {
        int col = n0 + wn * 32 + ni * 8 + (lane & 3) * 2;
        float b0 = 0.f, b1 = 0.f;
        if (bias) { b0 = __ldg(bias + col); b1 = __ldg(bias + col + 1); }
#pragma unroll
        for (int mi = 0; mi < 4; mi++) {
            int row = m0 + wm * 64 + mi * 16 + (lane >> 2);
            float v0 = acc[mi][ni][0] + b0, v1 = acc[mi][ni][1] + b1;
            float v2 = acc[mi][ni][2] + b0, v3 = acc[mi][ni][3] + b1;
            if (ACT == 2) {
                v0 = v0 > 0.f ? v0 : 0.01f * v0;
                v1 = v1 > 0.f ? v1 : 0.01f * v1;
                v2 = v2 > 0.f ? v2 : 0.01f * v2;
                v3 = v3 > 0.f ? v3 : 0.01f * v3;
            }
            *(float2*)(C + (size_t)row * N + col) = make_float2(v0, v1);
            *(float2*)(C + (size_t)(row + 8) * N + col) = make_float2(v2, v3);
        }
    }
}

// ---------------- pooling / head ------------------------------------------------
__global__ void pool_kernel() {
    int c = blockIdx.x, d = threadIdx.x;
    const __half* p = g_h + (size_t)c * NPC * HID + d;
    float s = 0.f;
#pragma unroll
    for (int j = 0; j < NPC; j++) s += __half2float(p[j * HID]);
    g_cm[c * HID + d] = __float2half(s * (1.0f / NPC));
}
__global__ void setpool_kernel() {
    int i = blockIdx.x * blockDim.x + threadIdx.x;
    int b = i >> 6, s = i & 63;
    float acc = 0.f;
#pragma unroll
    for (int c = 0; c < CPG; c++) {
        const float* t = g_tt + (size_t)(b * CPG + c) * KWC + s;
        float mx = -3.4e38f;
#pragma unroll
        for (int m = 0; m < MSET; m++) mx = fmaxf(mx, t[m * SDIM]);
        acc += mx;
    }
    g_pool[i] = acc;
}
__global__ void fc1_kernel(const float* __restrict__ w, const float* __restrict__ b) {
    __shared__ float sw[64 * 32];
    __shared__ float sb[32];
    int tid = threadIdx.x;
    for (int i = tid; i < 64 * 32; i += 256) sw[i] = w[i];
    if (tid < 32) sb[tid] = b[tid];
    __syncthreads();
    int r = blockIdx.x * 256 + tid;
    float acc[32];
#pragma unroll
    for (int o = 0; o < 32; o++) acc[o] = sb[o];
    const float* pr = g_pool + (size_t)r * 64;
    for (int d = 0; d < 64; d++) {
        float p = pr[d];
#pragma unroll
        for (int o = 0; o < 32; o++) acc[o] += p * sw[d * 32 + o];
    }
#pragma unroll
    for (int o = 0; o < 32; o++) g_tfc[r * 32 + o] = acc[o];
}
__global__ void stats_kernel() {
    __shared__ float ss[1024], sq[1024];
    int t = threadIdx.x;
    int col = t & 31, g = t >> 5;
    float s = 0.f, q = 0.f;
    for (int r = g; r < NGRAPH; r += 32) {
        float v = g_tfc[r * 32 + col];
        s += v; q += v * v;
    }
    ss[t] = s; sq[t] = q;
    __syncthreads();
    if (t < 32) {
        float S = 0.f, Q = 0.f;
#pragma unroll
        for (int gg = 0; gg < 32; gg++) { S += ss[gg * 32 + t]; Q += sq[gg * 32 + t]; }
        g_stats[t] = S; g_stats[32 + t] = Q;
    }
}
__global__ void fc2_kernel(const float* __restrict__ bng, const float* __restrict__ bnb,
                           const float* __restrict__ w2, const float* __restrict__ b2,
                           float* __restrict__ out) {
    int r = blockIdx.x * 256 + threadIdx.x;
    const float invB = 1.0f / NGRAPH;
    float l0 = b2[0], l1 = b2[1];
#pragma unroll
    for (int o = 0; o < 32; o++) {
        float mu  = g_stats[o] * invB;
        float var = g_stats[32 + o] * invB - mu * mu;
        float v = (g_tfc[r * 32 + o] - mu) * rsqrtf(var + 1e-5f) * bng[o] + bnb[o];
        v = v > 0.f ? v : 0.01f * v;
        l0 += v * w2[o * 2 + 0];
        l1 += v * w2[o * 2 + 1];
    }
    float m = fmaxf(l0, l1);
    float lse = m + logf(expf(l0 - m) + expf(l1 - m));
    out[r * 2 + 0] = l0 - lse;
    out[r * 2 + 1] = l1 - lse;
}

// ---------------- host launcher --------------------------------------------------
extern "C" void kernel_launch(void* const* d_in, const int* in_sizes, int n_in,
                              void* d_out, int out_size) {
    const float* x    = (const float*)d_in[0];
    const float* w0a  = (const float*)d_in[1];
    const float* b0a  = (const float*)d_in[2];
    const float* w0b  = (const float*)d_in[3];
    const float* b0b  = (const float*)d_in[4];
    const float* wra  = (const float*)d_in[5];
    const float* bra  = (const float*)d_in[6];
    const float* wrb  = (const float*)d_in[7];
    const float* brb  = (const float*)d_in[8];
    const float* Wc   = (const float*)d_in[9];
    const float* fc1w = (const float*)d_in[10];
    const float* fc1b = (const float*)d_in[11];
    const float* bng  = (const float*)d_in[12];
    const float* bnb  = (const float*)d_in[13];
    const float* fc2w = (const float*)d_in[14];
    const float* fc2b = (const float*)d_in[15];
    const int*   ei   = (const int*)d_in[16];
    const int* src = ei;
    const int* dst = ei + NEDGES;
    float* out = (float*)d_out;

    void* p;
    cudaGetSymbolAddress(&p, g_hsum); __half* hsum = (__half*)p;
    cudaGetSymbolAddress(&p, g_h);    __half* h    = (__half*)p;
    cudaGetSymbolAddress(&p, g_cm);   __half* cm   = (__half*)p;
    cudaGetSymbolAddress(&p, g_tt);   float*  tt   = (float*)p;
    cudaGetSymbolAddress(&p, g_wt);   __half* wt   = (__half*)p;

    // fused conv kernels: smem sizes
    const int SM_CONV0 = 128 * (INCH * 2 + 16) + 128 * (HID * 2 + 16) + 2 * WBUF;  // 122880
    const int SM_CONV  = 128 * (HID * 2 + 16) + 128 * (HID * 2 + 16) + 2 * WBUF;   // 155648
    cudaFuncSetAttribute((const void*)fused_mlp<INCH, 1>, cudaFuncAttributeMaxDynamicSharedMemorySize, SM_CONV0);
    cudaFuncSetAttribute((const void*)fused_mlp<HID, 1>,  cudaFuncAttributeMaxDynamicSharedMemorySize, SM_CONV);
    cudaFuncSetAttribute((const void*)fused_mlp<HID, 0>,  cudaFuncAttributeMaxDynamicSharedMemorySize, SM_CONV);
    cudaFuncSetAttribute((const void*)mma_gemm<2>, cudaFuncAttributeMaxDynamicSharedMemorySize, GEMM_SMEM);

    // ---- weight transpose (one launch) ----
    transpose_all<<<(WT_TOTAL + 255) / 256, 256>>>(w0a, w0b, wra, wrb, Wc);

    // ---- CSR build ----
    csr_zero <<<NBLK, 256>>>();
    csr_count<<<NEDGES / 256, 256>>>(dst);
    csr_scan1<<<NBLK, 256>>>();
    csr_scan2<<<1, 1024>>>();
    csr_scan3<<<NBLK, 256>>>();
    csr_fill <<<NEDGES / 256, 256>>>(src, dst);

    // ---- conv0 ----
    gather_f32<INCH><<<NNODES / 8, 256>>>(x);
    fused_mlp<INCH, 1><<<NNODES / 128, 256, SM_CONV0>>>(hsum, wt + OFF_W0A, b0a, wt + OFF_W0B, b0b, h);

    // ---- conv1 ----
    gather_f16<HID><<<NNODES / 8, 256>>>(h);
    fused_mlp<HID, 1><<<NNODES / 128, 256, SM_CONV>>>(hsum, wt + OFF_WRA0, bra, wt + OFF_WRB0, brb, h);

    // ---- conv2 ----
    gather_f16<HID><<<NNODES / 8, 256>>>(h);
    fused_mlp<HID, 0><<<NNODES / 128, 256, SM_CONV>>>(hsum, wt + OFF_WRA1, bra + HID, wt + OFF_WRB1, brb + HID, h);

    // ---- pooling ----
    pool_kernel<<<NCOMP, HID>>>();

    // ---- set-rep GEMM ----
    {
        dim3 grid(KWC / 128, NCOMP / 128);
        mma_gemm<2><<<grid, 256, GEMM_SMEM>>>(cm, wt + OFF_WC, nullptr, tt, HID, KWC);
    }
    setpool_kernel<<<(NGRAPH * SDIM) / 256, 256>>>();

    // ---- head ----
    fc1_kernel<<<NGRAPH / 256, 256>>>(fc1w, fc1b);
    stats_kernel<<<1, 1024>>>();
    fc2_kernel<<<NGRAPH / 256, 256>>>(bng, bnb, fc2w, fc2b, out);
}